// round 8
// baseline (speedup 1.0000x reference)
#include <cuda_runtime.h>
#include <math.h>

#define G        512
#define S        32
#define PTS      8
#define SEGS_PER (PTS - 1)           // 7
#define NSEG     (S * SEGS_PER)      // 224
#define TILE     16
#define NTHREADS 128                 // 8 thread-cols x 16 rows, 2 px/thread
#define TPR      (G / TILE)          // 32 tiles per row

// ---------------------------------------------------------------------------
// One 16x16 tile per 128-thread CTA. Cull phase classifies each surviving
// segment by the range of frac over the tile (frac is linear in p):
//   LINE   : frac in (0,1) tile-wide  -> darkness^2 = (A*px + B*py + C)^2
//   ENDPT  : frac <= 0 or >= 1        -> darkness^2 = |p - endpoint|^2 * sc
//   FULL   : frac boundary in tile    -> exact clamped-frac formula
// Warp-ballot compaction into three SMEM lists; render loops each list.
// ---------------------------------------------------------------------------
__global__ void __launch_bounds__(NTHREADS)
render_kernel(const float* __restrict__ strokes,
              const float* __restrict__ thick,
              float* __restrict__ out) {
    __shared__ float4 s_ln[NSEG];    // A, B, C, (unused)
    __shared__ float4 s_ep[NSEG];    // qx, qy, sc, (unused)
    __shared__ float4 s_fa[NSEG];    // vx, vy, ex, ey
    __shared__ float2 s_fb[NSEG];    // invd2, sc
    __shared__ int    s_nl, s_ne, s_nf;

    const int tid  = threadIdx.x;
    const int lane = tid & 31;
    const int wid  = tid >> 5;

    // ---- Issue segment loads early (latency hides under the first barrier) ----
    int    sA = (tid * 9363) >> 16;                // tid / 7
    int    iA = sA * PTS + (tid - sA * SEGS_PER);
    float2 pA0 = ((const float2*)strokes)[iA];
    float2 pA1 = ((const float2*)strokes)[iA + 1];
    float  tA  = thick[sA];

    int    segB = 128 + tid;
    float2 pB0 = make_float2(0.f, 0.f), pB1 = pB0;
    float  tB  = 0.f;
    if (wid < 3) {
        int sB = (segB * 9363) >> 16;
        int iB = sB * PTS + (segB - sB * SEGS_PER);
        pB0 = ((const float2*)strokes)[iB];
        pB1 = ((const float2*)strokes)[iB + 1];
        tB  = thick[sB];
    }

    if (tid == 0) { s_nl = 0; s_ne = 0; s_nf = 0; }
    __syncthreads();

    const int ti = blockIdx.y * TILE;              // row base (out stride G)
    const int tj = blockIdx.x * TILE;              // col base (contiguous)

    const float cx   = (float)ti + (TILE - 1) * 0.5f;
    const float cy   = (float)tj + (TILE - 1) * 0.5f;
    const float RMAX = (TILE - 1) * 0.5f * 1.41421356f + 1.0f;

    #define CULL_ROUND(P0, P1, TK)                                            \
    {                                                                         \
        float vx = __saturatef((P0).x) * (float)G;                            \
        float vy = __saturatef((P0).y) * (float)G;                            \
        float wx = __saturatef((P1).x) * (float)G;                            \
        float wy = __saturatef((P1).y) * (float)G;                            \
        float ex = wx - vx;                                                   \
        float ey = wy - vy;                                                   \
        float d2 = ex * ex + ey * ey;                                         \
        float invd2 = __fdividef(1.0f, d2 + 1e-5f);                           \
        float t  = fmaxf(fmaf((TK), 2.0f, 0.5f), 0.5f);                       \
        float r  = 2.0f * t;                                                  \
        float sc = __fdividef(1.0f, r * r);                                   \
        float dx  = cx - vx;                                                  \
        float dy  = cy - vy;                                                  \
        float dot = dx * ex + dy * ey;                                        \
        float frc = dot * invd2;                                              \
        float fr  = __saturatef(frc);                                         \
        float ddx = fmaf(-fr, ex, dx);                                        \
        float ddy = fmaf(-fr, ey, dy);                                        \
        float dq  = ddx * ddx + ddy * ddy;                                    \
        float thr = r + RMAX;                                                 \
        bool keep = (dq <= thr * thr);                                        \
        float fdev = RMAX * sqrtf(d2) * invd2;                                \
        float flo = frc - fdev;                                               \
        float fhi = frc + fdev;                                               \
        bool isline = keep && (flo > 1e-5f) && (fhi < 0.99999f);              \
        bool isendv = keep && !isline && (fhi < -1e-5f);                      \
        bool isendw = keep && !isline && (flo > 1.00001f);                    \
        bool isend  = isendv || isendw;                                       \
        bool isfull = keep && !isline && !isend;                              \
        unsigned bl = __ballot_sync(0xffffffffu, isline);                     \
        unsigned be = __ballot_sync(0xffffffffu, isend);                      \
        unsigned bf = __ballot_sync(0xffffffffu, isfull);                     \
        int basel = 0, basee = 0, basef = 0;                                  \
        if (lane == 0) {                                                      \
            if (bl) basel = atomicAdd(&s_nl, __popc(bl));                     \
            if (be) basee = atomicAdd(&s_ne, __popc(be));                     \
            if (bf) basef = atomicAdd(&s_nf, __popc(bf));                     \
        }                                                                     \
        basel = __shfl_sync(0xffffffffu, basel, 0);                           \
        basee = __shfl_sync(0xffffffffu, basee, 0);                           \
        basef = __shfl_sync(0xffffffffu, basef, 0);                           \
        unsigned pre = (1u << lane) - 1u;                                     \
        if (isline) {                                                         \
            float f = sqrtf(invd2 * sc);                                      \
            float A = f * ey;                                                 \
            float B = -f * ex;                                                \
            float C = f * (vy * ex - vx * ey);                                \
            s_ln[basel + __popc(bl & pre)] = make_float4(A, B, C, 0.f);       \
        } else if (isend) {                                                   \
            float qx = isendv ? vx : wx;                                      \
            float qy = isendv ? vy : wy;                                      \
            s_ep[basee + __popc(be & pre)] = make_float4(qx, qy, sc, 0.f);    \
        } else if (isfull) {                                                  \
            int p = basef + __popc(bf & pre);                                 \
            s_fa[p] = make_float4(vx, vy, ex, ey);                            \
            s_fb[p] = make_float2(invd2, sc);                                 \
        }                                                                     \
    }

    CULL_ROUND(pA0, pA1, tA);
    if (wid < 3) CULL_ROUND(pB0, pB1, tB);
    #undef CULL_ROUND

    __syncthreads();

    // ---- Render: 2 horizontally adjacent pixels per thread ----
    const int tx = tid & 7;                        // px cols 2tx, 2tx+1
    const int ty = tid >> 3;                       // row 0..15
    const float px  = (float)(ti + ty);
    const float py0 = (float)(tj + 2 * tx);
    const int nl = s_nl, ne = s_ne, nf = s_nf;

    float m0 = 1e30f;
    float m1 = 1e30f;

    // LINE: darkness^2 = (A*px + B*py + C)^2
    #pragma unroll 2
    for (int q = 0; q < nl; q++) {
        float4 L = s_ln[q];
        float val0 = fmaf(L.x, px, fmaf(L.y, py0, L.z));
        float val1 = val0 + L.y;
        m0 = fminf(m0, val0 * val0);
        m1 = fminf(m1, val1 * val1);
    }

    // ENDPOINT: darkness^2 = |p - q|^2 * sc
    #pragma unroll 2
    for (int q = 0; q < ne; q++) {
        float4 E = s_ep[q];
        float dx  = px - E.x;
        float dy0 = py0 - E.y;
        float dy1 = dy0 + 1.0f;
        float dxx = dx * dx;
        float dq0 = fmaf(dy0, dy0, dxx);
        float dq1 = fmaf(dy1, dy1, dxx);
        m0 = fminf(m0, dq0 * E.z);
        m1 = fminf(m1, dq1 * E.z);
    }

    // FULL: exact clamped-frac formula
    #pragma unroll 2
    for (int q = 0; q < nf; q++) {
        float4 a = s_fa[q];
        float2 b = s_fb[q];
        float dx   = px - a.x;
        float dy0  = py0 - a.y;
        float dy1  = dy0 + 1.0f;
        float dxez = dx * a.z;
        float dot0 = fmaf(dy0, a.w, dxez);
        float dot1 = dot0 + a.w;
        float fr0  = __saturatef(dot0 * b.x);
        float fr1  = __saturatef(dot1 * b.x);
        float ddx0 = fmaf(-fr0, a.z, dx);
        float ddy0 = fmaf(-fr0, a.w, dy0);
        float ddx1 = fmaf(-fr1, a.z, dx);
        float ddy1 = fmaf(-fr1, a.w, dy1);
        float dq0  = fmaf(ddx0, ddx0, ddy0 * ddy0);
        float dq1  = fmaf(ddx1, ddx1, ddy1 * ddy1);
        m0 = fminf(m0, dq0 * b.y);
        m1 = fminf(m1, dq1 * b.y);
    }

    float2 res = make_float2(fminf(sqrtf(m0), 1.0f), fminf(sqrtf(m1), 1.0f));
    *(float2*)(out + (ti + ty) * G + (tj + 2 * tx)) = res;
}

extern "C" void kernel_launch(void* const* d_in, const int* in_sizes, int n_in,
                              void* d_out, int out_size) {
    // metadata order: strokes [32,8,2] f32 (512 elems), thicknesses [32] f32.
    const float* strokes = (const float*)d_in[0];
    const float* thick   = (const float*)d_in[1];
    if (n_in >= 2 && in_sizes[0] == S && in_sizes[1] == S * PTS * 2) {
        strokes = (const float*)d_in[1];
        thick   = (const float*)d_in[0];
    }
    float* out = (float*)d_out;

    dim3 block(NTHREADS);
    dim3 grid(TPR, TPR);
    render_kernel<<<grid, block>>>(strokes, thick, out);
}